// round 1
// baseline (speedup 1.0000x reference)
#include <cuda_runtime.h>
#include <math.h>

// Problem constants
#define BB 8
#define NN 2048
#define CC 1024
#define HH 16
#define DD 64
#define MM (BB*NN)        // 16384 rows
#define HALFC (CC/2)      // 512 rope pairs
#define NSPLIT 8

// Scratch (device globals: allocation-free per harness rules)
__device__ float g_Q[MM*CC];
__device__ float g_K[MM*CC];
__device__ float g_V[MM*CC];
__device__ float g_O[MM*CC];
__device__ float g_kvp[NSPLIT*BB*HH*DD*DD];
__device__ float g_kmp[NSPLIT*BB*HH*DD];
__device__ float g_kv[BB*HH*DD*DD];
__device__ float g_km[BB*HH*DD];
__device__ float g_invfreq[HALFC];

// ---------------------------------------------------------------------------
// inv_freq[j] = theta^(-2j/C), computed in double for accuracy
__global__ void init_invfreq_kernel() {
    int j = threadIdx.x;
    if (j < HALFC)
        g_invfreq[j] = (float)(1.0 / pow(10000.0, (double)(2 * j) / (double)CC));
}

// ---------------------------------------------------------------------------
// GEMM: Y[m,n] = sum_k A[m,k] * W[n,k] + bias[n]  (A: MMxCC, W: CCxCC row-major)
// which: 0 -> g_Q (gelu+0.21), 1 -> g_K (gelu+0.21), 2 -> g_V (plain)
#define BM 128
#define BN 128
#define BK 16
#define BMP 132   // padded row stride (floats), 16B aligned, reduces STS conflicts

__global__ __launch_bounds__(256) void gemm_kernel(
    const float* __restrict__ A, const float* __restrict__ W,
    const float* __restrict__ bias, int which)
{
    __shared__ float As[BK][BMP];
    __shared__ float Bs[BK][BMP];
    float* __restrict__ Y = (which == 0) ? g_Q : (which == 1) ? g_K : g_V;
    const int mode = (which < 2) ? 1 : 0;

    int t  = threadIdx.x;
    int m0 = blockIdx.y * BM;
    int n0 = blockIdx.x * BN;
    int tx = t & 15, ty = t >> 4;

    float acc[8][8];
    #pragma unroll
    for (int i = 0; i < 8; i++)
        #pragma unroll
        for (int j = 0; j < 8; j++) acc[i][j] = 0.f;

    for (int k0 = 0; k0 < CC; k0 += BK) {
        #pragma unroll
        for (int ld = 0; ld < 2; ld++) {
            int idx = t + ld * 256;          // 0..511 float4 slots
            int r = idx >> 2, q = idx & 3;
            float4 va = *(const float4*)&A[(size_t)(m0 + r) * CC + k0 + q * 4];
            As[q*4+0][r] = va.x; As[q*4+1][r] = va.y;
            As[q*4+2][r] = va.z; As[q*4+3][r] = va.w;
            float4 vb = *(const float4*)&W[(size_t)(n0 + r) * CC + k0 + q * 4];
            Bs[q*4+0][r] = vb.x; Bs[q*4+1][r] = vb.y;
            Bs[q*4+2][r] = vb.z; Bs[q*4+3][r] = vb.w;
        }
        __syncthreads();
        #pragma unroll
        for (int kk = 0; kk < BK; kk++) {
            float ar[8], br[8];
            *(float4*)&ar[0] = *(float4*)&As[kk][ty * 8];
            *(float4*)&ar[4] = *(float4*)&As[kk][ty * 8 + 4];
            *(float4*)&br[0] = *(float4*)&Bs[kk][tx * 8];
            *(float4*)&br[4] = *(float4*)&Bs[kk][tx * 8 + 4];
            #pragma unroll
            for (int i = 0; i < 8; i++)
                #pragma unroll
                for (int j = 0; j < 8; j++)
                    acc[i][j] += ar[i] * br[j];
        }
        __syncthreads();
    }

    #pragma unroll
    for (int i = 0; i < 8; i++) {
        int row = m0 + ty * 8 + i;
        #pragma unroll
        for (int j = 0; j < 8; j++) {
            int col = n0 + tx * 8 + j;
            float y = acc[i][j] + bias[col];
            if (mode) {
                // exact GELU (erf form) + 0.21
                y = 0.5f * y * (1.f + erff(y * 0.7071067811865476f)) + 0.21f;
            }
            Y[(size_t)row * CC + col] = y;
        }
    }
}

// ---------------------------------------------------------------------------
// kv partial: per (b,h,split) accumulate  sum_n rope(k)[n,d]*v[n,e]  and sum_n k[n,d]
__global__ __launch_bounds__(256) void kv_partial_kernel() {
    int bh = blockIdx.x;             // 0..127
    int sp = blockIdx.y;             // 0..7
    int b = bh >> 4, h = bh & 15;
    int t = threadIdx.x;

    __shared__ float ks[32 * 64];
    __shared__ float krs[32 * 64];
    __shared__ float vs[32 * 64];

    int tx = t & 15, ty = t >> 4;
    float acc[4][4];
    #pragma unroll
    for (int i = 0; i < 4; i++)
        #pragma unroll
        for (int j = 0; j < 4; j++) acc[i][j] = 0.f;
    float ksum = 0.f;

    for (int ch = 0; ch < 8; ch++) {
        int n0 = sp * 256 + ch * 32;
        #pragma unroll
        for (int ld = 0; ld < 2; ld++) {
            int idx = t + ld * 256;      // 0..511 float4
            int r = idx >> 4, c4 = idx & 15;
            size_t gofs = (size_t)(b * NN + n0 + r) * CC + h * DD + c4 * 4;
            *(float4*)&ks[r * 64 + c4 * 4] = *(const float4*)&g_K[gofs];
            *(float4*)&vs[r * 64 + c4 * 4] = *(const float4*)&g_V[gofs];
        }
        __syncthreads();
        // rope(k) -> krs   (pairs within head: jj local, global pair = h*32+jj)
        #pragma unroll
        for (int pp = 0; pp < 4; pp++) {
            int p = t + pp * 256;        // 0..1023
            int r = p >> 5, jj = p & 31;
            float a  = ks[r * 64 + 2 * jj];
            float bv = ks[r * 64 + 2 * jj + 1];
            float ang = (float)(n0 + r) * g_invfreq[h * 32 + jj];
            float sv, cv;
            sincosf(ang, &sv, &cv);
            krs[r * 64 + 2 * jj]     = a * cv - bv * sv;
            krs[r * 64 + 2 * jj + 1] = bv * cv + a * sv;
        }
        if (t < 64) {                    // raw-k column sum (for k_mean)
            #pragma unroll
            for (int r = 0; r < 32; r++) ksum += ks[r * 64 + t];
        }
        __syncthreads();
        #pragma unroll
        for (int nn = 0; nn < 32; nn++) {
            float4 kr4 = *(float4*)&krs[nn * 64 + ty * 4];
            float4 vv4 = *(float4*)&vs[nn * 64 + tx * 4];
            float kr[4] = {kr4.x, kr4.y, kr4.z, kr4.w};
            float vv[4] = {vv4.x, vv4.y, vv4.z, vv4.w};
            #pragma unroll
            for (int i = 0; i < 4; i++)
                #pragma unroll
                for (int j = 0; j < 4; j++)
                    acc[i][j] += kr[i] * vv[j];
        }
        __syncthreads();
    }

    float* kvp = &g_kvp[((size_t)sp * (BB * HH) + bh) * (DD * DD)];
    #pragma unroll
    for (int i = 0; i < 4; i++)
        #pragma unroll
        for (int j = 0; j < 4; j++)
            kvp[(ty * 4 + i) * DD + tx * 4 + j] = acc[i][j];
    if (t < 64)
        g_kmp[((size_t)sp * (BB * HH) + bh) * DD + t] = ksum;
}

// deterministic reduce of the NSPLIT partials; applies 1/n scaling
__global__ __launch_bounds__(256) void kv_reduce_kernel() {
    int bh = blockIdx.x;
    int t = threadIdx.x;
    const float inv = 1.f / (float)NN;
    for (int i = t; i < DD * DD; i += 256) {
        float s = 0.f;
        #pragma unroll
        for (int sp = 0; sp < NSPLIT; sp++)
            s += g_kvp[((size_t)sp * (BB * HH) + bh) * (DD * DD) + i];
        g_kv[(size_t)bh * (DD * DD) + i] = s * inv;
    }
    if (t < DD) {
        float s = 0.f;
        #pragma unroll
        for (int sp = 0; sp < NSPLIT; sp++)
            s += g_kmp[((size_t)sp * (BB * HH) + bh) * DD + t];
        g_km[(size_t)bh * DD + t] = s * inv;
    }
}

// ---------------------------------------------------------------------------
// out[b,n,h,e] = z * sum_d rope(q)[n,d] * kv[b,h,d,e],  z = 1/(q.k_mean + 1e-6)
__global__ __launch_bounds__(256) void out_kernel() {
    int bh = blockIdx.x;
    int b = bh >> 4, h = bh & 15;
    int n0 = blockIdx.y * 32;
    int t = threadIdx.x;

    __shared__ float kvs[DD * DD];   // 16 KB
    __shared__ float kms[DD];
    __shared__ float qs[16 * 64];
    __shared__ float qrs[16 * 64];

    #pragma unroll
    for (int ld = 0; ld < 4; ld++) {
        int i4 = t + ld * 256;       // float4 idx 0..1023
        *(float4*)&kvs[i4 * 4] = *(const float4*)&g_kv[(size_t)bh * (DD * DD) + i4 * 4];
    }
    if (t < DD) kms[t] = g_km[(size_t)bh * DD + t];
    __syncthreads();

    int tg = t & 15, rr = t >> 4;    // 16 e-groups x 16 rows
    for (int ig = 0; ig < 2; ig++) {
        int n = n0 + ig * 16 + rr;
        *(float4*)&qs[rr * 64 + tg * 4] =
            *(const float4*)&g_Q[(size_t)(b * NN + n) * CC + h * DD + tg * 4];
        __syncthreads();
        #pragma unroll
        for (int pp = 0; pp < 2; pp++) {
            int p = t + pp * 256;    // 0..511
            int r = p >> 5, jj = p & 31;
            float a  = qs[r * 64 + 2 * jj];
            float bv = qs[r * 64 + 2 * jj + 1];
            float ang = (float)(n0 + ig * 16 + r) * g_invfreq[h * 32 + jj];
            float sv, cv;
            sincosf(ang, &sv, &cv);
            qrs[r * 64 + 2 * jj]     = a * cv - bv * sv;
            qrs[r * 64 + 2 * jj + 1] = bv * cv + a * sv;
        }
        // z from non-rope q (qs already synced; reads overlap qrs writes on disjoint arrays)
        float zacc = 0.f;
        #pragma unroll
        for (int d = 0; d < DD; d++) zacc += qs[rr * 64 + d] * kms[d];
        float z = 1.f / (zacc + 1e-6f);
        __syncthreads();
        float4 o = {0.f, 0.f, 0.f, 0.f};
        #pragma unroll
        for (int d = 0; d < DD; d++) {
            float qv = qrs[rr * 64 + d];
            float4 kvv = *(float4*)&kvs[d * 64 + tg * 4];
            o.x += qv * kvv.x; o.y += qv * kvv.y;
            o.z += qv * kvv.z; o.w += qv * kvv.w;
        }
        o.x *= z; o.y *= z; o.z *= z; o.w *= z;
        *(float4*)&g_O[(size_t)(b * NN + n) * CC + h * DD + tg * 4] = o;
        __syncthreads();
    }
}

// ---------------------------------------------------------------------------
// residual + LayerNorm (biased var, eps 1e-12)
__global__ __launch_bounds__(256) void ln_kernel(
    const float* __restrict__ x, const float* __restrict__ gamma,
    const float* __restrict__ beta, float* __restrict__ out)
{
    int row = blockIdx.x;
    int t = threadIdx.x;
    float4 a  = *(const float4*)&g_O[(size_t)row * CC + t * 4];
    float4 xv = *(const float4*)&x[(size_t)row * CC + t * 4];
    float4 r;
    r.x = a.x + xv.x; r.y = a.y + xv.y; r.z = a.z + xv.z; r.w = a.w + xv.w;
    float s  = r.x + r.y + r.z + r.w;
    float sq = r.x * r.x + r.y * r.y + r.z * r.z + r.w * r.w;
    #pragma unroll
    for (int off = 16; off; off >>= 1) {
        s  += __shfl_xor_sync(0xffffffffu, s, off);
        sq += __shfl_xor_sync(0xffffffffu, sq, off);
    }
    __shared__ float ss[8], ssq[8];
    __shared__ float mean_s, rstd_s;
    int w = t >> 5, lane = t & 31;
    if (lane == 0) { ss[w] = s; ssq[w] = sq; }
    __syncthreads();
    if (t == 0) {
        float S = 0.f, SQ = 0.f;
        #pragma unroll
        for (int i = 0; i < 8; i++) { S += ss[i]; SQ += ssq[i]; }
        float mean = S * (1.f / (float)CC);
        float var  = SQ * (1.f / (float)CC) - mean * mean;
        mean_s = mean;
        rstd_s = rsqrtf(var + 1e-12f);
    }
    __syncthreads();
    float mean = mean_s, rstd = rstd_s;
    float4 g  = *(const float4*)&gamma[t * 4];
    float4 be = *(const float4*)&beta[t * 4];
    float4 o;
    o.x = (r.x - mean) * rstd * g.x + be.x;
    o.y = (r.y - mean) * rstd * g.y + be.y;
    o.z = (r.z - mean) * rstd * g.z + be.z;
    o.w = (r.w - mean) * rstd * g.w + be.w;
    *(float4*)&out[(size_t)row * CC + t * 4] = o;
}

// ---------------------------------------------------------------------------
extern "C" void kernel_launch(void* const* d_in, const int* in_sizes, int n_in,
                              void* d_out, int out_size) {
    const float* x     = (const float*)d_in[0];
    const float* Wq    = (const float*)d_in[1];
    const float* bq    = (const float*)d_in[2];
    const float* Wk    = (const float*)d_in[3];
    const float* bk    = (const float*)d_in[4];
    const float* Wv    = (const float*)d_in[5];
    const float* bv    = (const float*)d_in[6];
    const float* gamma = (const float*)d_in[7];
    const float* beta  = (const float*)d_in[8];
    float* out = (float*)d_out;

    init_invfreq_kernel<<<1, 512>>>();

    dim3 ggrid(CC / BN, MM / BM);              // (8, 128)
    gemm_kernel<<<ggrid, 256>>>(x, Wq, bq, 0); // -> g_Q (gelu+0.21)
    gemm_kernel<<<ggrid, 256>>>(x, Wk, bk, 1); // -> g_K (gelu+0.21)
    gemm_kernel<<<ggrid, 256>>>(x, Wv, bv, 2); // -> g_V

    kv_partial_kernel<<<dim3(BB * HH, NSPLIT), 256>>>();
    kv_reduce_kernel<<<BB * HH, 256>>>();
    out_kernel<<<dim3(BB * HH, NN / 32), 256>>>();
    ln_kernel<<<MM, 256>>>(x, gamma, beta, out);
}

// round 2
// speedup vs baseline: 1.2420x; 1.2420x over previous
#include <cuda_runtime.h>
#include <cuda_bf16.h>
#include <math.h>
#include <stdint.h>

// Problem constants
#define BB 8
#define NN 2048
#define CC 1024
#define HH 16
#define DD 64
#define MM (BB*NN)        // 16384 rows
#define HALFC (CC/2)
#define NSPLIT 8

// Scratch (device globals: allocation-free per harness rules)
__device__ float g_Q[MM*CC];
__device__ float g_K[MM*CC];
__device__ float g_V[MM*CC];
__device__ float g_O[MM*CC];
__device__ float g_kvp[NSPLIT*BB*HH*DD*DD];
__device__ float g_kmp[NSPLIT*BB*HH*DD];
__device__ float g_kv[BB*HH*DD*DD];
__device__ float g_km[BB*HH*DD];
__device__ float g_invfreq[HALFC];

// bf16 split operands
__device__ __nv_bfloat16 g_Ahi[MM*CC];
__device__ __nv_bfloat16 g_Alo[MM*CC];
__device__ __nv_bfloat16 g_Whi[3][CC*CC];
__device__ __nv_bfloat16 g_Wlo[3][CC*CC];

// ---------------------------------------------------------------------------
__global__ void init_invfreq_kernel() {
    int j = threadIdx.x;
    if (j < HALFC)
        g_invfreq[j] = (float)(1.0 / pow(10000.0, (double)(2 * j) / (double)CC));
}

// ---------------------------------------------------------------------------
// Split fp32 -> bf16 hi/lo
__global__ __launch_bounds__(256) void split_x_kernel(const float* __restrict__ x) {
    size_t i = (size_t)blockIdx.x * 256 + threadIdx.x;   // float4 index
    float4 v = *(const float4*)(x + i * 4);
    float f[4] = {v.x, v.y, v.z, v.w};
    union { __nv_bfloat16 h[4]; uint2 u; } H, L;
    #pragma unroll
    for (int k = 0; k < 4; k++) {
        __nv_bfloat16 hh = __float2bfloat16(f[k]);
        H.h[k] = hh;
        L.h[k] = __float2bfloat16(f[k] - __bfloat162float(hh));
    }
    *(uint2*)&g_Ahi[i * 4] = H.u;
    *(uint2*)&g_Alo[i * 4] = L.u;
}

__global__ __launch_bounds__(256) void split_w_kernel(const float* __restrict__ W, int idx) {
    size_t i = (size_t)blockIdx.x * 256 + threadIdx.x;
    float4 v = *(const float4*)(W + i * 4);
    float f[4] = {v.x, v.y, v.z, v.w};
    union { __nv_bfloat16 h[4]; uint2 u; } H, L;
    #pragma unroll
    for (int k = 0; k < 4; k++) {
        __nv_bfloat16 hh = __float2bfloat16(f[k]);
        H.h[k] = hh;
        L.h[k] = __float2bfloat16(f[k] - __bfloat162float(hh));
    }
    *(uint2*)&g_Whi[idx][i * 4] = H.u;
    *(uint2*)&g_Wlo[idx][i * 4] = L.u;
}

// ---------------------------------------------------------------------------
// Tensor-core GEMM: Y[m,n] = sum_k A[m,k]*W[n,k] + bias[n], bf16x3 split in fp32 acc
// Tile 128x128, BK=32, 8 warps (4m x 2n), each warp 32m x 64n.
#define SA 40   // padded smem row stride (bf16 elems); 80B stride -> conflict-free

__device__ __forceinline__ void ldsm4(unsigned* r, uint32_t addr) {
    asm volatile("ldmatrix.sync.aligned.m8n8.x4.shared.b16 {%0,%1,%2,%3},[%4];\n"
                 : "=r"(r[0]), "=r"(r[1]), "=r"(r[2]), "=r"(r[3]) : "r"(addr));
}
__device__ __forceinline__ void mma16816(float* d, const unsigned* a, const unsigned* b) {
    asm volatile("mma.sync.aligned.m16n8k16.row.col.f32.bf16.bf16.f32 "
                 "{%0,%1,%2,%3},{%4,%5,%6,%7},{%8,%9},{%0,%1,%2,%3};\n"
                 : "+f"(d[0]), "+f"(d[1]), "+f"(d[2]), "+f"(d[3])
                 : "r"(a[0]), "r"(a[1]), "r"(a[2]), "r"(a[3]), "r"(b[0]), "r"(b[1]));
}

__global__ __launch_bounds__(256, 2) void gemm_mma_kernel(
    const float* __restrict__ bias, int which)
{
    __shared__ __align__(16) __nv_bfloat16 smA[2][128 * SA];
    __shared__ __align__(16) __nv_bfloat16 smW[2][128 * SA];

    float* __restrict__ Y = (which == 0) ? g_Q : (which == 1) ? g_K : g_V;
    const bool gel = (which < 2);

    const int t = threadIdx.x;
    const int lane = t & 31, warp = t >> 5;
    const int wm = warp & 3, wn = warp >> 2;     // 4 x 2 warp grid
    const int m0 = blockIdx.y * 128, n0 = blockIdx.x * 128;

    const uint32_t sA0 = (uint32_t)__cvta_generic_to_shared(&smA[0][0]);
    const uint32_t sW0 = (uint32_t)__cvta_generic_to_shared(&smW[0][0]);
    const uint32_t bufSz = 128 * SA * 2;

    float acc[2][8][4];
    #pragma unroll
    for (int mt = 0; mt < 2; mt++)
        #pragma unroll
        for (int j = 0; j < 8; j++)
            #pragma unroll
            for (int r = 0; r < 4; r++) acc[mt][j][r] = 0.f;

    auto prefetch = [&](int it, int buf) {
        int ph = it >> 5;                        // 0,1,2 -> (hi,hi),(hi,lo),(lo,hi)
        const __nv_bfloat16* Ap = (ph < 2) ? g_Ahi : g_Alo;
        const __nv_bfloat16* Wp = (ph == 1) ? g_Wlo[which] : g_Whi[which];
        int kk = (it & 31) << 5;
        #pragma unroll
        for (int i = 0; i < 4; i++) {
            int c = t + i * 256;                 // 0..1023 16B chunks
            int isW = c >> 9, cc = c & 511;
            int row = cc >> 2, seg = cc & 3;
            const __nv_bfloat16* gp = isW
                ? Wp + (size_t)(n0 + row) * CC + kk + seg * 8
                : Ap + (size_t)(m0 + row) * CC + kk + seg * 8;
            uint32_t sp = (isW ? sW0 : sA0) + buf * bufSz + (row * SA + seg * 8) * 2;
            asm volatile("cp.async.cg.shared.global [%0],[%1],16;\n" :: "r"(sp), "l"(gp));
        }
        asm volatile("cp.async.commit_group;\n");
    };

    const int aRow = lane & 15, aCol = (lane >> 4) << 3;
    const int bRow = (lane & 7) + ((lane >> 4) << 3), bCol = ((lane >> 3) & 1) << 3;

    prefetch(0, 0);
    #pragma unroll 1
    for (int it = 0; it < 96; ++it) {
        int buf = it & 1;
        if (it < 95) {
            prefetch(it + 1, buf ^ 1);
            asm volatile("cp.async.wait_group 1;\n");
        } else {
            asm volatile("cp.async.wait_group 0;\n");
        }
        __syncthreads();
        #pragma unroll
        for (int ks = 0; ks < 2; ++ks) {
            unsigned a[2][4], bf[4][4];
            #pragma unroll
            for (int mt = 0; mt < 2; ++mt) {
                uint32_t ad = sA0 + buf * bufSz +
                    ((wm * 32 + mt * 16 + aRow) * SA + ks * 16 + aCol) * 2;
                ldsm4(a[mt], ad);
            }
            #pragma unroll
            for (int np = 0; np < 4; ++np) {
                uint32_t ad = sW0 + buf * bufSz +
                    ((wn * 64 + np * 16 + bRow) * SA + ks * 16 + bCol) * 2;
                ldsm4(bf[np], ad);
            }
            #pragma unroll
            for (int mt = 0; mt < 2; ++mt)
                #pragma unroll
                for (int j = 0; j < 8; ++j)
                    mma16816(acc[mt][j], a[mt], &bf[j >> 1][(j & 1) * 2]);
        }
        __syncthreads();
    }

    // Epilogue: bias (+ exact GELU + 0.21 for Q/K)
    const int gid = lane >> 2, tid2 = lane & 3;
    #pragma unroll
    for (int mt = 0; mt < 2; ++mt) {
        int r0 = m0 + wm * 32 + mt * 16 + gid;
        #pragma unroll
        for (int j = 0; j < 8; ++j) {
            int col = n0 + wn * 64 + j * 8 + tid2 * 2;
            float b0 = __ldg(&bias[col]), b1 = __ldg(&bias[col + 1]);
            float y0 = acc[mt][j][0] + b0, y1 = acc[mt][j][1] + b1;
            float y2 = acc[mt][j][2] + b0, y3 = acc[mt][j][3] + b1;
            if (gel) {
                y0 = 0.5f * y0 * (1.f + erff(y0 * 0.7071067811865476f)) + 0.21f;
                y1 = 0.5f * y1 * (1.f + erff(y1 * 0.7071067811865476f)) + 0.21f;
                y2 = 0.5f * y2 * (1.f + erff(y2 * 0.7071067811865476f)) + 0.21f;
                y3 = 0.5f * y3 * (1.f + erff(y3 * 0.7071067811865476f)) + 0.21f;
            }
            *(float2*)&Y[(size_t)r0 * CC + col] = make_float2(y0, y1);
            *(float2*)&Y[(size_t)(r0 + 8) * CC + col] = make_float2(y2, y3);
        }
    }
}

// ---------------------------------------------------------------------------
// kv partial: per (b,h,split) accumulate  sum_n rope(k)[n,d]*v[n,e]  and sum_n k[n,d]
__global__ __launch_bounds__(256) void kv_partial_kernel() {
    int bh = blockIdx.x;
    int sp = blockIdx.y;
    int b = bh >> 4, h = bh & 15;
    int t = threadIdx.x;

    __shared__ float ks[32 * 64];
    __shared__ float krs[32 * 64];
    __shared__ float vs[32 * 64];

    int tx = t & 15, ty = t >> 4;
    float acc[4][4];
    #pragma unroll
    for (int i = 0; i < 4; i++)
        #pragma unroll
        for (int j = 0; j < 4; j++) acc[i][j] = 0.f;
    float ksum = 0.f;

    for (int ch = 0; ch < 8; ch++) {
        int n0 = sp * 256 + ch * 32;
        #pragma unroll
        for (int ld = 0; ld < 2; ld++) {
            int idx = t + ld * 256;
            int r = idx >> 4, c4 = idx & 15;
            size_t gofs = (size_t)(b * NN + n0 + r) * CC + h * DD + c4 * 4;
            *(float4*)&ks[r * 64 + c4 * 4] = *(const float4*)&g_K[gofs];
            *(float4*)&vs[r * 64 + c4 * 4] = *(const float4*)&g_V[gofs];
        }
        __syncthreads();
        #pragma unroll
        for (int pp = 0; pp < 4; pp++) {
            int p = t + pp * 256;
            int r = p >> 5, jj = p & 31;
            float a  = ks[r * 64 + 2 * jj];
            float bv = ks[r * 64 + 2 * jj + 1];
            float ang = (float)(n0 + r) * g_invfreq[h * 32 + jj];
            float sv, cv;
            sincosf(ang, &sv, &cv);
            krs[r * 64 + 2 * jj]     = a * cv - bv * sv;
            krs[r * 64 + 2 * jj + 1] = bv * cv + a * sv;
        }
        if (t < 64) {
            #pragma unroll
            for (int r = 0; r < 32; r++) ksum += ks[r * 64 + t];
        }
        __syncthreads();
        #pragma unroll
        for (int nn = 0; nn < 32; nn++) {
            float4 kr4 = *(float4*)&krs[nn * 64 + ty * 4];
            float4 vv4 = *(float4*)&vs[nn * 64 + tx * 4];
            float kr[4] = {kr4.x, kr4.y, kr4.z, kr4.w};
            float vv[4] = {vv4.x, vv4.y, vv4.z, vv4.w};
            #pragma unroll
            for (int i = 0; i < 4; i++)
                #pragma unroll
                for (int j = 0; j < 4; j++)
                    acc[i][j] += kr[i] * vv[j];
        }
        __syncthreads();
    }

    float* kvp = &g_kvp[((size_t)sp * (BB * HH) + bh) * (DD * DD)];
    #pragma unroll
    for (int i = 0; i < 4; i++)
        #pragma unroll
        for (int j = 0; j < 4; j++)
            kvp[(ty * 4 + i) * DD + tx * 4 + j] = acc[i][j];
    if (t < 64)
        g_kmp[((size_t)sp * (BB * HH) + bh) * DD + t] = ksum;
}

__global__ __launch_bounds__(256) void kv_reduce_kernel() {
    int bh = blockIdx.x;
    int t = threadIdx.x;
    const float inv = 1.f / (float)NN;
    for (int i = t; i < DD * DD; i += 256) {
        float s = 0.f;
        #pragma unroll
        for (int sp = 0; sp < NSPLIT; sp++)
            s += g_kvp[((size_t)sp * (BB * HH) + bh) * (DD * DD) + i];
        g_kv[(size_t)bh * (DD * DD) + i] = s * inv;
    }
    if (t < DD) {
        float s = 0.f;
        #pragma unroll
        for (int sp = 0; sp < NSPLIT; sp++)
            s += g_kmp[((size_t)sp * (BB * HH) + bh) * DD + t];
        g_km[(size_t)bh * DD + t] = s * inv;
    }
}

// ---------------------------------------------------------------------------
__global__ __launch_bounds__(256) void out_kernel() {
    int bh = blockIdx.x;
    int b = bh >> 4, h = bh & 15;
    int n0 = blockIdx.y * 32;
    int t = threadIdx.x;

    __shared__ float kvs[DD * DD];
    __shared__ float kms[DD];
    __shared__ float qs[16 * 64];
    __shared__ float qrs[16 * 64];

    #pragma unroll
    for (int ld = 0; ld < 4; ld++) {
        int i4 = t + ld * 256;
        *(float4*)&kvs[i4 * 4] = *(const float4*)&g_kv[(size_t)bh * (DD * DD) + i4 * 4];
    }
    if (t < DD) kms[t] = g_km[(size_t)bh * DD + t];
    __syncthreads();

    int tg = t & 15, rr = t >> 4;
    for (int ig = 0; ig < 2; ig++) {
        int n = n0 + ig * 16 + rr;
        *(float4*)&qs[rr * 64 + tg * 4] =
            *(const float4*)&g_Q[(size_t)(b * NN + n) * CC + h * DD + tg * 4];
        __syncthreads();
        #pragma unroll
        for (int pp = 0; pp < 2; pp++) {
            int p = t + pp * 256;
            int r = p >> 5, jj = p & 31;
            float a  = qs[r * 64 + 2 * jj];
            float bv = qs[r * 64 + 2 * jj + 1];
            float ang = (float)(n0 + ig * 16 + r) * g_invfreq[h * 32 + jj];
            float sv, cv;
            sincosf(ang, &sv, &cv);
            qrs[r * 64 + 2 * jj]     = a * cv - bv * sv;
            qrs[r * 64 + 2 * jj + 1] = bv * cv + a * sv;
        }
        float zacc = 0.f;
        #pragma unroll
        for (int d = 0; d < DD; d++) zacc += qs[rr * 64 + d] * kms[d];
        float z = 1.f / (zacc + 1e-6f);
        __syncthreads();
        float4 o = {0.f, 0.f, 0.f, 0.f};
        #pragma unroll
        for (int d = 0; d < DD; d++) {
            float qv = qrs[rr * 64 + d];
            float4 kvv = *(float4*)&kvs[d * 64 + tg * 4];
            o.x += qv * kvv.x; o.y += qv * kvv.y;
            o.z += qv * kvv.z; o.w += qv * kvv.w;
        }
        o.x *= z; o.y *= z; o.z *= z; o.w *= z;
        *(float4*)&g_O[(size_t)(b * NN + n) * CC + h * DD + tg * 4] = o;
        __syncthreads();
    }
}

// ---------------------------------------------------------------------------
__global__ __launch_bounds__(256) void ln_kernel(
    const float* __restrict__ x, const float* __restrict__ gamma,
    const float* __restrict__ beta, float* __restrict__ out)
{
    int row = blockIdx.x;
    int t = threadIdx.x;
    float4 a  = *(const float4*)&g_O[(size_t)row * CC + t * 4];
    float4 xv = *(const float4*)&x[(size_t)row * CC + t * 4];
    float4 r;
    r.x = a.x + xv.x; r.y = a.y + xv.y; r.z = a.z + xv.z; r.w = a.w + xv.w;
    float s  = r.x + r.y + r.z + r.w;
    float sq = r.x * r.x + r.y * r.y + r.z * r.z + r.w * r.w;
    #pragma unroll
    for (int off = 16; off; off >>= 1) {
        s  += __shfl_xor_sync(0xffffffffu, s, off);
        sq += __shfl_xor_sync(0xffffffffu, sq, off);
    }
    __shared__ float ss[8], ssq[8];
    __shared__ float mean_s, rstd_s;
    int w = t >> 5, lane = t & 31;
    if (lane == 0) { ss[w] = s; ssq[w] = sq; }
    __syncthreads();
    if (t == 0) {
        float S = 0.f, SQ = 0.f;
        #pragma unroll
        for (int i = 0; i < 8; i++) { S += ss[i]; SQ += ssq[i]; }
        float mean = S * (1.f / (float)CC);
        float var  = SQ * (1.f / (float)CC) - mean * mean;
        mean_s = mean;
        rstd_s = rsqrtf(var + 1e-12f);
    }
    __syncthreads();
    float mean = mean_s, rstd = rstd_s;
    float4 g  = *(const float4*)&gamma[t * 4];
    float4 be = *(const float4*)&beta[t * 4];
    float4 o;
    o.x = (r.x - mean) * rstd * g.x + be.x;
    o.y = (r.y - mean) * rstd * g.y + be.y;
    o.z = (r.z - mean) * rstd * g.z + be.z;
    o.w = (r.w - mean) * rstd * g.w + be.w;
    *(float4*)&out[(size_t)row * CC + t * 4] = o;
}

// ---------------------------------------------------------------------------
extern "C" void kernel_launch(void* const* d_in, const int* in_sizes, int n_in,
                              void* d_out, int out_size) {
    const float* x     = (const float*)d_in[0];
    const float* Wq    = (const float*)d_in[1];
    const float* bq    = (const float*)d_in[2];
    const float* Wk    = (const float*)d_in[3];
    const float* bk    = (const float*)d_in[4];
    const float* Wv    = (const float*)d_in[5];
    const float* bv    = (const float*)d_in[6];
    const float* gamma = (const float*)d_in[7];
    const float* beta  = (const float*)d_in[8];
    float* out = (float*)d_out;

    init_invfreq_kernel<<<1, 512>>>();

    split_x_kernel<<<MM * CC / 1024, 256>>>(x);
    split_w_kernel<<<CC * CC / 1024, 256>>>(Wq, 0);
    split_w_kernel<<<CC * CC / 1024, 256>>>(Wk, 1);
    split_w_kernel<<<CC * CC / 1024, 256>>>(Wv, 2);

    dim3 ggrid(CC / 128, MM / 128);                  // (8, 128)
    gemm_mma_kernel<<<ggrid, 256>>>(bq, 0);          // -> g_Q (gelu+0.21)
    gemm_mma_kernel<<<ggrid, 256>>>(bk, 1);          // -> g_K (gelu+0.21)
    gemm_mma_kernel<<<ggrid, 256>>>(bv, 2);          // -> g_V

    kv_partial_kernel<<<dim3(BB * HH, NSPLIT), 256>>>();
    kv_reduce_kernel<<<BB * HH, 256>>>();
    out_kernel<<<dim3(BB * HH, NN / 32), 256>>>();
    ln_kernel<<<MM, 256>>>(x, gamma, beta, out);
}

// round 4
// speedup vs baseline: 2.0731x; 1.6692x over previous
#include <cuda_runtime.h>
#include <cuda_bf16.h>
#include <math.h>
#include <stdint.h>

// Problem constants
#define BB 8
#define NN 2048
#define CC 1024
#define HH 16
#define DD 64
#define MM (BB*NN)        // 16384 rows
#define HALFC (CC/2)
#define NSPLIT 8

// Scratch (device globals: allocation-free per harness rules)
__device__ float g_Q[MM*CC];
__device__ float g_K[MM*CC];
__device__ float g_V[MM*CC];
__device__ float g_O[MM*CC];
__device__ float g_kvp[NSPLIT*BB*HH*DD*DD];
__device__ float g_kmp[NSPLIT*BB*HH*DD];
__device__ float g_kv[BB*HH*DD*DD];
__device__ float g_km[BB*HH*DD];
__device__ float g_invfreq[HALFC];

// bf16 split operands
__device__ __nv_bfloat16 g_Ahi[MM*CC];
__device__ __nv_bfloat16 g_Alo[MM*CC];
__device__ __nv_bfloat16 g_Whi[3][CC*CC];
__device__ __nv_bfloat16 g_Wlo[3][CC*CC];

// ---------------------------------------------------------------------------
__global__ void init_invfreq_kernel() {
    int j = threadIdx.x;
    if (j < HALFC)
        g_invfreq[j] = (float)(1.0 / pow(10000.0, (double)(2 * j) / (double)CC));
}

// ---------------------------------------------------------------------------
// Split fp32 -> bf16 hi/lo
__global__ __launch_bounds__(256) void split_x_kernel(const float* __restrict__ x) {
    size_t i = (size_t)blockIdx.x * 256 + threadIdx.x;   // float4 index
    float4 v = *(const float4*)(x + i * 4);
    float f[4] = {v.x, v.y, v.z, v.w};
    union { __nv_bfloat16 h[4]; uint2 u; } H, L;
    #pragma unroll
    for (int k = 0; k < 4; k++) {
        __nv_bfloat16 hh = __float2bfloat16(f[k]);
        H.h[k] = hh;
        L.h[k] = __float2bfloat16(f[k] - __bfloat162float(hh));
    }
    *(uint2*)&g_Ahi[i * 4] = H.u;
    *(uint2*)&g_Alo[i * 4] = L.u;
}

__global__ __launch_bounds__(256) void split_w_kernel(
    const float* __restrict__ W0, const float* __restrict__ W1,
    const float* __restrict__ W2)
{
    int idx = blockIdx.y;
    const float* __restrict__ W = (idx == 0) ? W0 : (idx == 1) ? W1 : W2;
    size_t i = (size_t)blockIdx.x * 256 + threadIdx.x;
    float4 v = *(const float4*)(W + i * 4);
    float f[4] = {v.x, v.y, v.z, v.w};
    union { __nv_bfloat16 h[4]; uint2 u; } H, L;
    #pragma unroll
    for (int k = 0; k < 4; k++) {
        __nv_bfloat16 hh = __float2bfloat16(f[k]);
        H.h[k] = hh;
        L.h[k] = __float2bfloat16(f[k] - __bfloat162float(hh));
    }
    *(uint2*)&g_Whi[idx][i * 4] = H.u;
    *(uint2*)&g_Wlo[idx][i * 4] = L.u;
}

// ---------------------------------------------------------------------------
// Tensor-core GEMM (HMMA mma.sync): Y[m,n] = sum_k A[m,k]*W[n,k] + bias[n]
// bf16x3 split, fp32 acc. Tile 128x128, BK=32, 3-stage cp.async pipeline.
// Fused: blockIdx.z selects Q/K/V.
#define SA 40                 // padded smem row stride (bf16), conflict-free
#define STG 3
#define GBUF (128 * SA)       // bf16 elems per operand per stage
#define GEMM_SMEM (STG * 2 * GBUF * 2)   // bytes = 61440

__device__ __forceinline__ void ldsm4(unsigned* r, uint32_t addr) {
    asm volatile("ldmatrix.sync.aligned.m8n8.x4.shared.b16 {%0,%1,%2,%3},[%4];\n"
                 : "=r"(r[0]), "=r"(r[1]), "=r"(r[2]), "=r"(r[3]) : "r"(addr));
}
__device__ __forceinline__ void mma16816(float* d, const unsigned* a, const unsigned* b) {
    asm volatile("mma.sync.aligned.m16n8k16.row.col.f32.bf16.bf16.f32 "
                 "{%0,%1,%2,%3},{%4,%5,%6,%7},{%8,%9},{%0,%1,%2,%3};\n"
                 : "+f"(d[0]), "+f"(d[1]), "+f"(d[2]), "+f"(d[3])
                 : "r"(a[0]), "r"(a[1]), "r"(a[2]), "r"(a[3]), "r"(b[0]), "r"(b[1]));
}

__global__ __launch_bounds__(256, 2) void gemm_mma_kernel(
    const float* __restrict__ bq, const float* __restrict__ bk,
    const float* __restrict__ bv)
{
    extern __shared__ __nv_bfloat16 sm[];    // [STG][A|W][GBUF]
    const int which = blockIdx.z;
    const float* __restrict__ bias = (which == 0) ? bq : (which == 1) ? bk : bv;
    float* __restrict__ Y = (which == 0) ? g_Q : (which == 1) ? g_K : g_V;
    const bool gel = (which < 2);
    const __nv_bfloat16* __restrict__ Wh = g_Whi[which];
    const __nv_bfloat16* __restrict__ Wl = g_Wlo[which];

    const int t = threadIdx.x;
    const int lane = t & 31, warp = t >> 5;
    const int wm = warp & 3, wn = warp >> 2;     // 4 x 2 warp grid
    const int m0 = blockIdx.y * 128, n0 = blockIdx.x * 128;

    const uint32_t sBase = (uint32_t)__cvta_generic_to_shared(sm);
    const uint32_t stgSz = 2u * GBUF * 2u;       // bytes per stage (A+W)

    float acc[2][8][4];
    #pragma unroll
    for (int mt = 0; mt < 2; mt++)
        #pragma unroll
        for (int j = 0; j < 8; j++)
            #pragma unroll
            for (int r = 0; r < 4; r++) acc[mt][j][r] = 0.f;

    auto prefetch = [&](int it, int stg) {
        int ph = it >> 5;                        // 0,1,2 -> (hi,hi),(hi,lo),(lo,hi)
        const __nv_bfloat16* Ap = (ph < 2) ? g_Ahi : g_Alo;
        const __nv_bfloat16* Wp = (ph == 1) ? Wl : Wh;
        int kk = (it & 31) << 5;
        uint32_t sA = sBase + stg * stgSz;
        uint32_t sW = sA + GBUF * 2;
        #pragma unroll
        for (int i = 0; i < 4; i++) {
            int c = t + i * 256;                 // 0..1023 16B chunks
            int isW = c >> 9, cc = c & 511;
            int row = cc >> 2, seg = cc & 3;
            const __nv_bfloat16* gp = isW
                ? Wp + (size_t)(n0 + row) * CC + kk + seg * 8
                : Ap + (size_t)(m0 + row) * CC + kk + seg * 8;
            uint32_t sp = (isW ? sW : sA) + (row * SA + seg * 8) * 2;
            asm volatile("cp.async.cg.shared.global [%0],[%1],16;\n" :: "r"(sp), "l"(gp));
        }
        asm volatile("cp.async.commit_group;\n");
    };

    const int aRow = lane & 15, aCol = (lane >> 4) << 3;
    const int bRow = (lane & 7) + ((lane >> 4) << 3), bCol = ((lane >> 3) & 1) << 3;

    prefetch(0, 0);
    prefetch(1, 1);

    #pragma unroll 1
    for (int it = 0; it < 96; ++it) {
        if (it < 94) asm volatile("cp.async.wait_group 1;\n");
        else         asm volatile("cp.async.wait_group 0;\n");
        __syncthreads();
        if (it + 2 < 96) prefetch(it + 2, (it + 2) % 3);

        const uint32_t sA = sBase + (it % 3) * stgSz;
        const uint32_t sW = sA + GBUF * 2;
        #pragma unroll
        for (int ks = 0; ks < 2; ++ks) {
            unsigned a[2][4], bf[4][4];
            #pragma unroll
            for (int mt = 0; mt < 2; ++mt)
                ldsm4(a[mt], sA + ((wm * 32 + mt * 16 + aRow) * SA + ks * 16 + aCol) * 2);
            #pragma unroll
            for (int np = 0; np < 4; ++np)
                ldsm4(bf[np], sW + ((wn * 64 + np * 16 + bRow) * SA + ks * 16 + bCol) * 2);
            #pragma unroll
            for (int mt = 0; mt < 2; ++mt)
                #pragma unroll
                for (int j = 0; j < 8; ++j)
                    mma16816(acc[mt][j], a[mt], &bf[j >> 1][(j & 1) * 2]);
        }
    }

    // Epilogue: bias (+ exact GELU + 0.21 for Q/K)
    const int gid = lane >> 2, tid2 = lane & 3;
    #pragma unroll
    for (int mt = 0; mt < 2; ++mt) {
        int r0 = m0 + wm * 32 + mt * 16 + gid;
        #pragma unroll
        for (int j = 0; j < 8; ++j) {
            int col = n0 + wn * 64 + j * 8 + tid2 * 2;
            float b0 = __ldg(&bias[col]), b1 = __ldg(&bias[col + 1]);
            float y0 = acc[mt][j][0] + b0, y1 = acc[mt][j][1] + b1;
            float y2 = acc[mt][j][2] + b0, y3 = acc[mt][j][3] + b1;
            if (gel) {
                y0 = 0.5f * y0 * (1.f + erff(y0 * 0.7071067811865476f)) + 0.21f;
                y1 = 0.5f * y1 * (1.f + erff(y1 * 0.7071067811865476f)) + 0.21f;
                y2 = 0.5f * y2 * (1.f + erff(y2 * 0.7071067811865476f)) + 0.21f;
                y3 = 0.5f * y3 * (1.f + erff(y3 * 0.7071067811865476f)) + 0.21f;
            }
            *(float2*)&Y[(size_t)r0 * CC + col] = make_float2(y0, y1);
            *(float2*)&Y[(size_t)(r0 + 8) * CC + col] = make_float2(y2, y3);
        }
    }
}

// ---------------------------------------------------------------------------
// kv partial: per (b,h,split) accumulate  sum_n rope(k)[n,d]*v[n,e]  and sum_n k[n,d]
__global__ __launch_bounds__(256) void kv_partial_kernel() {
    int bh = blockIdx.x;
    int sp = blockIdx.y;
    int b = bh >> 4, h = bh & 15;
    int t = threadIdx.x;

    __shared__ float ks[32 * 64];
    __shared__ float krs[32 * 64];
    __shared__ float vs[32 * 64];

    int tx = t & 15, ty = t >> 4;
    float acc[4][4];
    #pragma unroll
    for (int i = 0; i < 4; i++)
        #pragma unroll
        for (int j = 0; j < 4; j++) acc[i][j] = 0.f;
    float ksum = 0.f;

    for (int ch = 0; ch < 8; ch++) {
        int n0 = sp * 256 + ch * 32;
        #pragma unroll
        for (int ld = 0; ld < 2; ld++) {
            int idx = t + ld * 256;
            int r = idx >> 4, c4 = idx & 15;
            size_t gofs = (size_t)(b * NN + n0 + r) * CC + h * DD + c4 * 4;
            *(float4*)&ks[r * 64 + c4 * 4] = *(const float4*)&g_K[gofs];
            *(float4*)&vs[r * 64 + c4 * 4] = *(const float4*)&g_V[gofs];
        }
        __syncthreads();
        #pragma unroll
        for (int pp = 0; pp < 4; pp++) {
            int p = t + pp * 256;
            int r = p >> 5, jj = p & 31;
            float a  = ks[r * 64 + 2 * jj];
            float bv = ks[r * 64 + 2 * jj + 1];
            float ang = (float)(n0 + r) * g_invfreq[h * 32 + jj];
            float sv, cv;
            sincosf(ang, &sv, &cv);
            krs[r * 64 + 2 * jj]     = a * cv - bv * sv;
            krs[r * 64 + 2 * jj + 1] = bv * cv + a * sv;
        }
        if (t < 64) {
            #pragma unroll
            for (int r = 0; r < 32; r++) ksum += ks[r * 64 + t];
        }
        __syncthreads();
        #pragma unroll
        for (int nn = 0; nn < 32; nn++) {
            float4 kr4 = *(float4*)&krs[nn * 64 + ty * 4];
            float4 vv4 = *(float4*)&vs[nn * 64 + tx * 4];
            float kr[4] = {kr4.x, kr4.y, kr4.z, kr4.w};
            float vv[4] = {vv4.x, vv4.y, vv4.z, vv4.w};
            #pragma unroll
            for (int i = 0; i < 4; i++)
                #pragma unroll
                for (int j = 0; j < 4; j++)
                    acc[i][j] += kr[i] * vv[j];
        }
        __syncthreads();
    }

    float* kvp = &g_kvp[((size_t)sp * (BB * HH) + bh) * (DD * DD)];
    #pragma unroll
    for (int i = 0; i < 4; i++)
        #pragma unroll
        for (int j = 0; j < 4; j++)
            kvp[(ty * 4 + i) * DD + tx * 4 + j] = acc[i][j];
    if (t < 64)
        g_kmp[((size_t)sp * (BB * HH) + bh) * DD + t] = ksum;
}

__global__ __launch_bounds__(256) void kv_reduce_kernel() {
    int bh = blockIdx.x;
    int t = threadIdx.x;
    const float inv = 1.f / (float)NN;
    for (int i = t; i < DD * DD; i += 256) {
        float s = 0.f;
        #pragma unroll
        for (int sp = 0; sp < NSPLIT; sp++)
            s += g_kvp[((size_t)sp * (BB * HH) + bh) * (DD * DD) + i];
        g_kv[(size_t)bh * (DD * DD) + i] = s * inv;
    }
    if (t < DD) {
        float s = 0.f;
        #pragma unroll
        for (int sp = 0; sp < NSPLIT; sp++)
            s += g_kmp[((size_t)sp * (BB * HH) + bh) * DD + t];
        g_km[(size_t)bh * DD + t] = s * inv;
    }
}

// ---------------------------------------------------------------------------
__global__ __launch_bounds__(256) void out_kernel() {
    int bh = blockIdx.x;
    int b = bh >> 4, h = bh & 15;
    int n0 = blockIdx.y * 32;
    int t = threadIdx.x;

    __shared__ float kvs[DD * DD];
    __shared__ float kms[DD];
    __shared__ float qs[16 * 64];
    __shared__ float qrs[16 * 64];

    #pragma unroll
    for (int ld = 0; ld < 4; ld++) {
        int i4 = t + ld * 256;
        *(float4*)&kvs[i4 * 4] = *(const float4*)&g_kv[(size_t)bh * (DD * DD) + i4 * 4];
    }
    if (t < DD) kms[t] = g_km[(size_t)bh * DD + t];
    __syncthreads();

    int tg = t & 15, rr = t >> 4;
    for (int ig = 0; ig < 2; ig++) {
        int n = n0 + ig * 16 + rr;
        *(float4*)&qs[rr * 64 + tg * 4] =
            *(const float4*)&g_Q[(size_t)(b * NN + n) * CC + h * DD + tg * 4];
        __syncthreads();
        #pragma unroll
        for (int pp = 0; pp < 2; pp++) {
            int p = t + pp * 256;
            int r = p >> 5, jj = p & 31;
            float a  = qs[r * 64 + 2 * jj];
            float bv = qs[r * 64 + 2 * jj + 1];
            float ang = (float)(n0 + ig * 16 + r) * g_invfreq[h * 32 + jj];
            float sv, cv;
            sincosf(ang, &sv, &cv);
            qrs[r * 64 + 2 * jj]     = a * cv - bv * sv;
            qrs[r * 64 + 2 * jj + 1] = bv * cv + a * sv;
        }
        float zacc = 0.f;
        #pragma unroll
        for (int d = 0; d < DD; d++) zacc += qs[rr * 64 + d] * kms[d];
        float z = 1.f / (zacc + 1e-6f);
        __syncthreads();
        float4 o = {0.f, 0.f, 0.f, 0.f};
        #pragma unroll
        for (int d = 0; d < DD; d++) {
            float qv = qrs[rr * 64 + d];
            float4 kvv = *(float4*)&kvs[d * 64 + tg * 4];
            o.x += qv * kvv.x; o.y += qv * kvv.y;
            o.z += qv * kvv.z; o.w += qv * kvv.w;
        }
        o.x *= z; o.y *= z; o.z *= z; o.w *= z;
        *(float4*)&g_O[(size_t)(b * NN + n) * CC + h * DD + tg * 4] = o;
        __syncthreads();
    }
}

// ---------------------------------------------------------------------------
__global__ __launch_bounds__(256) void ln_kernel(
    const float* __restrict__ x, const float* __restrict__ gamma,
    const float* __restrict__ beta, float* __restrict__ out)
{
    int row = blockIdx.x;
    int t = threadIdx.x;
    float4 a  = *(const float4*)&g_O[(size_t)row * CC + t * 4];
    float4 xv = *(const float4*)&x[(size_t)row * CC + t * 4];
    float4 r;
    r.x = a.x + xv.x; r.y = a.y + xv.y; r.z = a.z + xv.z; r.w = a.w + xv.w;
    float s  = r.x + r.y + r.z + r.w;
    float sq = r.x * r.x + r.y * r.y + r.z * r.z + r.w * r.w;
    #pragma unroll
    for (int off = 16; off; off >>= 1) {
        s  += __shfl_xor_sync(0xffffffffu, s, off);
        sq += __shfl_xor_sync(0xffffffffu, sq, off);
    }
    __shared__ float ss[8], ssq[8];
    __shared__ float mean_s, rstd_s;
    int w = t >> 5, lane = t & 31;
    if (lane == 0) { ss[w] = s; ssq[w] = sq; }
    __syncthreads();
    if (t == 0) {
        float S = 0.f, SQ = 0.f;
        #pragma unroll
        for (int i = 0; i < 8; i++) { S += ss[i]; SQ += ssq[i]; }
        float mean = S * (1.f / (float)CC);
        float var  = SQ * (1.f / (float)CC) - mean * mean;
        mean_s = mean;
        rstd_s = rsqrtf(var + 1e-12f);
    }
    __syncthreads();
    float mean = mean_s, rstd = rstd_s;
    float4 g  = *(const float4*)&gamma[t * 4];
    float4 be = *(const float4*)&beta[t * 4];
    float4 o;
    o.x = (r.x - mean) * rstd * g.x + be.x;
    o.y = (r.y - mean) * rstd * g.y + be.y;
    o.z = (r.z - mean) * rstd * g.z + be.z;
    o.w = (r.w - mean) * rstd * g.w + be.w;
    *(float4*)&out[(size_t)row * CC + t * 4] = o;
}

// ---------------------------------------------------------------------------
extern "C" void kernel_launch(void* const* d_in, const int* in_sizes, int n_in,
                              void* d_out, int out_size) {
    const float* x     = (const float*)d_in[0];
    const float* Wq    = (const float*)d_in[1];
    const float* bq    = (const float*)d_in[2];
    const float* Wk    = (const float*)d_in[3];
    const float* bk    = (const float*)d_in[4];
    const float* Wv    = (const float*)d_in[5];
    const float* bv    = (const float*)d_in[6];
    const float* gamma = (const float*)d_in[7];
    const float* beta  = (const float*)d_in[8];
    float* out = (float*)d_out;

    init_invfreq_kernel<<<1, 512>>>();

    split_x_kernel<<<MM * CC / 1024, 256>>>(x);
    split_w_kernel<<<dim3(CC * CC / 1024, 3), 256>>>(Wq, Wk, Wv);

    cudaFuncSetAttribute(gemm_mma_kernel,
                         cudaFuncAttributeMaxDynamicSharedMemorySize, GEMM_SMEM);
    dim3 ggrid(CC / 128, MM / 128, 3);               // (8, 128, 3)
    gemm_mma_kernel<<<ggrid, 256, GEMM_SMEM>>>(bq, bk, bv);

    kv_partial_kernel<<<dim3(BB * HH, NSPLIT), 256>>>();
    kv_reduce_kernel<<<BB * HH, 256>>>();
    out_kernel<<<dim3(BB * HH, NN / 32), 256>>>();
    ln_kernel<<<MM, 256>>>(x, gamma, beta, out);
}

// round 5
// speedup vs baseline: 2.2387x; 1.0799x over previous
#include <cuda_runtime.h>
#include <cuda_bf16.h>
#include <math.h>
#include <stdint.h>

// Problem constants
#define BB 8
#define NN 2048
#define CC 1024
#define HH 16
#define DD 64
#define MM (BB*NN)        // 16384 rows
#define HALFC (CC/2)
#define NSPLIT 8

// Scratch (device globals: allocation-free per harness rules)
__device__ float g_Q[MM*CC];
__device__ float g_K[MM*CC];
__device__ float g_V[MM*CC];
__device__ float g_O[MM*CC];
__device__ float g_kvp[NSPLIT*BB*HH*DD*DD];
__device__ float g_kmp[NSPLIT*BB*HH*DD];
__device__ float g_kv[BB*HH*DD*DD];
__device__ float g_km[BB*HH*DD];
__device__ float g_invfreq[HALFC];

// bf16 split operands
__device__ __nv_bfloat16 g_Ahi[MM*CC];
__device__ __nv_bfloat16 g_Alo[MM*CC];
__device__ __nv_bfloat16 g_Whi[3][CC*CC];
__device__ __nv_bfloat16 g_Wlo[3][CC*CC];

// ---------------------------------------------------------------------------
__global__ void init_invfreq_kernel() {
    int j = threadIdx.x;
    if (j < HALFC)
        g_invfreq[j] = (float)(1.0 / pow(10000.0, (double)(2 * j) / (double)CC));
}

// ---------------------------------------------------------------------------
// Split fp32 -> bf16 hi/lo
__global__ __launch_bounds__(256) void split_x_kernel(const float* __restrict__ x) {
    size_t i = (size_t)blockIdx.x * 256 + threadIdx.x;   // float4 index
    float4 v = *(const float4*)(x + i * 4);
    float f[4] = {v.x, v.y, v.z, v.w};
    union { __nv_bfloat16 h[4]; uint2 u; } H, L;
    #pragma unroll
    for (int k = 0; k < 4; k++) {
        __nv_bfloat16 hh = __float2bfloat16(f[k]);
        H.h[k] = hh;
        L.h[k] = __float2bfloat16(f[k] - __bfloat162float(hh));
    }
    *(uint2*)&g_Ahi[i * 4] = H.u;
    *(uint2*)&g_Alo[i * 4] = L.u;
}

__global__ __launch_bounds__(256) void split_w_kernel(
    const float* __restrict__ W0, const float* __restrict__ W1,
    const float* __restrict__ W2)
{
    int idx = blockIdx.y;
    const float* __restrict__ W = (idx == 0) ? W0 : (idx == 1) ? W1 : W2;
    size_t i = (size_t)blockIdx.x * 256 + threadIdx.x;
    float4 v = *(const float4*)(W + i * 4);
    float f[4] = {v.x, v.y, v.z, v.w};
    union { __nv_bfloat16 h[4]; uint2 u; } H, L;
    #pragma unroll
    for (int k = 0; k < 4; k++) {
        __nv_bfloat16 hh = __float2bfloat16(f[k]);
        H.h[k] = hh;
        L.h[k] = __float2bfloat16(f[k] - __bfloat162float(hh));
    }
    *(uint2*)&g_Whi[idx][i * 4] = H.u;
    *(uint2*)&g_Wlo[idx][i * 4] = L.u;
}

// ---------------------------------------------------------------------------
// Tensor-core GEMM (HMMA mma.sync): Y[m,n] = sum_k A[m,k]*W[n,k] + bias[n]
// bf16x3 split, fp32 acc. Tile 128x128, BK=64, 2-stage cp.async pipeline,
// ONE __syncthreads per iteration. blockIdx.z selects Q/K/V.
#define SA 72                      // padded smem row stride (bf16): 144B, conflict-free
#define OPSZ (128 * SA * 2)        // bytes per operand per stage = 18432
#define STGSZ (2 * OPSZ)           // bytes per stage (A+W)       = 36864
#define GEMM_SMEM (2 * STGSZ)      // 73728
#define NIT 48                     // 3 split passes x (1024/64)

__device__ __forceinline__ void ldsm4(unsigned* r, uint32_t addr) {
    asm volatile("ldmatrix.sync.aligned.m8n8.x4.shared.b16 {%0,%1,%2,%3},[%4];\n"
                 : "=r"(r[0]), "=r"(r[1]), "=r"(r[2]), "=r"(r[3]) : "r"(addr));
}
__device__ __forceinline__ void mma16816(float* d, const unsigned* a, const unsigned* b) {
    asm volatile("mma.sync.aligned.m16n8k16.row.col.f32.bf16.bf16.f32 "
                 "{%0,%1,%2,%3},{%4,%5,%6,%7},{%8,%9},{%0,%1,%2,%3};\n"
                 : "+f"(d[0]), "+f"(d[1]), "+f"(d[2]), "+f"(d[3])
                 : "r"(a[0]), "r"(a[1]), "r"(a[2]), "r"(a[3]), "r"(b[0]), "r"(b[1]));
}

__global__ __launch_bounds__(256, 2) void gemm_mma_kernel(
    const float* __restrict__ bq, const float* __restrict__ bk,
    const float* __restrict__ bv)
{
    extern __shared__ __nv_bfloat16 sm[];
    const int which = blockIdx.z;
    const float* __restrict__ bias = (which == 0) ? bq : (which == 1) ? bk : bv;
    float* __restrict__ Y = (which == 0) ? g_Q : (which == 1) ? g_K : g_V;
    const bool gel = (which < 2);
    const __nv_bfloat16* __restrict__ Wh = g_Whi[which];
    const __nv_bfloat16* __restrict__ Wl = g_Wlo[which];

    const int t = threadIdx.x;
    const int lane = t & 31, warp = t >> 5;
    const int wm = warp & 3, wn = warp >> 2;     // 4 x 2 warp grid, warp tile 32x64
    const int m0 = blockIdx.y * 128, n0 = blockIdx.x * 128;

    const uint32_t sBase = (uint32_t)__cvta_generic_to_shared(sm);

    float acc[2][8][4];
    #pragma unroll
    for (int mt = 0; mt < 2; mt++)
        #pragma unroll
        for (int j = 0; j < 8; j++)
            #pragma unroll
            for (int r = 0; r < 4; r++) acc[mt][j][r] = 0.f;

    // it: 0..47.  phase = it/16: 0 Ahi*Whi, 1 Ahi*Wlo, 2 Alo*Whi. kk = (it%16)*64.
    auto prefetch = [&](int it, int stg) {
        int ph = it >> 4;
        const __nv_bfloat16* Ap = (ph < 2) ? g_Ahi : g_Alo;
        const __nv_bfloat16* Wp = (ph == 1) ? Wl : Wh;
        int kk = (it & 15) << 6;
        uint32_t sA = sBase + stg * STGSZ;
        uint32_t sW = sA + OPSZ;
        #pragma unroll
        for (int i = 0; i < 8; i++) {
            int c = t + i * 256;                 // 0..2047 16B chunks
            int isW = c >> 10, cc = c & 1023;    // 1024 chunks per operand
            int row = cc >> 3, seg = cc & 7;     // 128 rows x 8 segs(16B)
            const __nv_bfloat16* gp = isW
                ? Wp + (size_t)(n0 + row) * CC + kk + seg * 8
                : Ap + (size_t)(m0 + row) * CC + kk + seg * 8;
            uint32_t sp = (isW ? sW : sA) + (row * SA + seg * 8) * 2;
            asm volatile("cp.async.cg.shared.global [%0],[%1],16;\n" :: "r"(sp), "l"(gp));
        }
        asm volatile("cp.async.commit_group;\n");
    };

    const int aRow = lane & 15, aCol = (lane >> 4) << 3;
    const int bRow = (lane & 7) + ((lane >> 4) << 3), bCol = ((lane >> 3) & 1) << 3;

    prefetch(0, 0);

    #pragma unroll 1
    for (int it = 0; it < NIT; ++it) {
        asm volatile("cp.async.wait_group 0;\n");
        __syncthreads();
        // Safe to refill the other stage: every warp passed compute(it-1).
        if (it + 1 < NIT) prefetch(it + 1, (it + 1) & 1);

        const uint32_t sA = sBase + (it & 1) * STGSZ;
        const uint32_t sW = sA + OPSZ;
        #pragma unroll
        for (int ks = 0; ks < 4; ++ks) {
            unsigned a[2][4], bf[4][4];
            #pragma unroll
            for (int mt = 0; mt < 2; ++mt)
                ldsm4(a[mt], sA + ((wm * 32 + mt * 16 + aRow) * SA + ks * 16 + aCol) * 2);
            #pragma unroll
            for (int np = 0; np < 4; ++np)
                ldsm4(bf[np], sW + ((wn * 64 + np * 16 + bRow) * SA + ks * 16 + bCol) * 2);
            #pragma unroll
            for (int mt = 0; mt < 2; ++mt)
                #pragma unroll
                for (int j = 0; j < 8; ++j)
                    mma16816(acc[mt][j], a[mt], &bf[j >> 1][(j & 1) * 2]);
        }
    }

    // Epilogue: bias (+ exact GELU + 0.21 for Q/K)
    const int gid = lane >> 2, tid2 = lane & 3;
    #pragma unroll
    for (int mt = 0; mt < 2; ++mt) {
        int r0 = m0 + wm * 32 + mt * 16 + gid;
        #pragma unroll
        for (int j = 0; j < 8; ++j) {
            int col = n0 + wn * 64 + j * 8 + tid2 * 2;
            float b0 = __ldg(&bias[col]), b1 = __ldg(&bias[col + 1]);
            float y0 = acc[mt][j][0] + b0, y1 = acc[mt][j][1] + b1;
            float y2 = acc[mt][j][2] + b0, y3 = acc[mt][j][3] + b1;
            if (gel) {
                y0 = 0.5f * y0 * (1.f + erff(y0 * 0.7071067811865476f)) + 0.21f;
                y1 = 0.5f * y1 * (1.f + erff(y1 * 0.7071067811865476f)) + 0.21f;
                y2 = 0.5f * y2 * (1.f + erff(y2 * 0.7071067811865476f)) + 0.21f;
                y3 = 0.5f * y3 * (1.f + erff(y3 * 0.7071067811865476f)) + 0.21f;
            }
            *(float2*)&Y[(size_t)r0 * CC + col] = make_float2(y0, y1);
            *(float2*)&Y[(size_t)(r0 + 8) * CC + col] = make_float2(y2, y3);
        }
    }
}

// ---------------------------------------------------------------------------
// kv partial: per (b,h,split) accumulate  sum_n rope(k)[n,d]*v[n,e]  and sum_n k[n,d]
__global__ __launch_bounds__(256) void kv_partial_kernel() {
    int bh = blockIdx.x;
    int sp = blockIdx.y;
    int b = bh >> 4, h = bh & 15;
    int t = threadIdx.x;

    __shared__ float ks[32 * 64];
    __shared__ float krs[32 * 64];
    __shared__ float vs[32 * 64];

    int tx = t & 15, ty = t >> 4;
    float acc[4][4];
    #pragma unroll
    for (int i = 0; i < 4; i++)
        #pragma unroll
        for (int j = 0; j < 4; j++) acc[i][j] = 0.f;
    float ksum = 0.f;

    for (int ch = 0; ch < 8; ch++) {
        int n0 = sp * 256 + ch * 32;
        #pragma unroll
        for (int ld = 0; ld < 2; ld++) {
            int idx = t + ld * 256;
            int r = idx >> 4, c4 = idx & 15;
            size_t gofs = (size_t)(b * NN + n0 + r) * CC + h * DD + c4 * 4;
            *(float4*)&ks[r * 64 + c4 * 4] = *(const float4*)&g_K[gofs];
            *(float4*)&vs[r * 64 + c4 * 4] = *(const float4*)&g_V[gofs];
        }
        __syncthreads();
        #pragma unroll
        for (int pp = 0; pp < 4; pp++) {
            int p = t + pp * 256;
            int r = p >> 5, jj = p & 31;
            float a  = ks[r * 64 + 2 * jj];
            float bv = ks[r * 64 + 2 * jj + 1];
            float ang = (float)(n0 + r) * g_invfreq[h * 32 + jj];
            float sv, cv;
            sincosf(ang, &sv, &cv);
            krs[r * 64 + 2 * jj]     = a * cv - bv * sv;
            krs[r * 64 + 2 * jj + 1] = bv * cv + a * sv;
        }
        if (t < 64) {
            #pragma unroll
            for (int r = 0; r < 32; r++) ksum += ks[r * 64 + t];
        }
        __syncthreads();
        #pragma unroll
        for (int nn = 0; nn < 32; nn++) {
            float4 kr4 = *(float4*)&krs[nn * 64 + ty * 4];
            float4 vv4 = *(float4*)&vs[nn * 64 + tx * 4];
            float kr[4] = {kr4.x, kr4.y, kr4.z, kr4.w};
            float vv[4] = {vv4.x, vv4.y, vv4.z, vv4.w};
            #pragma unroll
            for (int i = 0; i < 4; i++)
                #pragma unroll
                for (int j = 0; j < 4; j++)
                    acc[i][j] += kr[i] * vv[j];
        }
        __syncthreads();
    }

    float* kvp = &g_kvp[((size_t)sp * (BB * HH) + bh) * (DD * DD)];
    #pragma unroll
    for (int i = 0; i < 4; i++)
        #pragma unroll
        for (int j = 0; j < 4; j++)
            kvp[(ty * 4 + i) * DD + tx * 4 + j] = acc[i][j];
    if (t < 64)
        g_kmp[((size_t)sp * (BB * HH) + bh) * DD + t] = ksum;
}

__global__ __launch_bounds__(256) void kv_reduce_kernel() {
    int bh = blockIdx.x;
    int t = threadIdx.x;
    const float inv = 1.f / (float)NN;
    for (int i = t; i < DD * DD; i += 256) {
        float s = 0.f;
        #pragma unroll
        for (int sp = 0; sp < NSPLIT; sp++)
            s += g_kvp[((size_t)sp * (BB * HH) + bh) * (DD * DD) + i];
        g_kv[(size_t)bh * (DD * DD) + i] = s * inv;
    }
    if (t < DD) {
        float s = 0.f;
        #pragma unroll
        for (int sp = 0; sp < NSPLIT; sp++)
            s += g_kmp[((size_t)sp * (BB * HH) + bh) * DD + t];
        g_km[(size_t)bh * DD + t] = s * inv;
    }
}

// ---------------------------------------------------------------------------
__global__ __launch_bounds__(256) void out_kernel() {
    int bh = blockIdx.x;
    int b = bh >> 4, h = bh & 15;
    int n0 = blockIdx.y * 32;
    int t = threadIdx.x;

    __shared__ float kvs[DD * DD];
    __shared__ float kms[DD];
    __shared__ float qs[16 * 64];
    __shared__ float qrs[16 * 64];

    #pragma unroll
    for (int ld = 0; ld < 4; ld++) {
        int i4 = t + ld * 256;
        *(float4*)&kvs[i4 * 4] = *(const float4*)&g_kv[(size_t)bh * (DD * DD) + i4 * 4];
    }
    if (t < DD) kms[t] = g_km[(size_t)bh * DD + t];
    __syncthreads();

    int tg = t & 15, rr = t >> 4;
    for (int ig = 0; ig < 2; ig++) {
        int n = n0 + ig * 16 + rr;
        *(float4*)&qs[rr * 64 + tg * 4] =
            *(const float4*)&g_Q[(size_t)(b * NN + n) * CC + h * DD + tg * 4];
        __syncthreads();
        #pragma unroll
        for (int pp = 0; pp < 2; pp++) {
            int p = t + pp * 256;
            int r = p >> 5, jj = p & 31;
            float a  = qs[r * 64 + 2 * jj];
            float bv = qs[r * 64 + 2 * jj + 1];
            float ang = (float)(n0 + ig * 16 + r) * g_invfreq[h * 32 + jj];
            float sv, cv;
            sincosf(ang, &sv, &cv);
            qrs[r * 64 + 2 * jj]     = a * cv - bv * sv;
            qrs[r * 64 + 2 * jj + 1] = bv * cv + a * sv;
        }
        float zacc = 0.f;
        #pragma unroll
        for (int d = 0; d < DD; d++) zacc += qs[rr * 64 + d] * kms[d];
        float z = 1.f / (zacc + 1e-6f);
        __syncthreads();
        float4 o = {0.f, 0.f, 0.f, 0.f};
        #pragma unroll
        for (int d = 0; d < DD; d++) {
            float qv = qrs[rr * 64 + d];
            float4 kvv = *(float4*)&kvs[d * 64 + tg * 4];
            o.x += qv * kvv.x; o.y += qv * kvv.y;
            o.z += qv * kvv.z; o.w += qv * kvv.w;
        }
        o.x *= z; o.y *= z; o.z *= z; o.w *= z;
        *(float4*)&g_O[(size_t)(b * NN + n) * CC + h * DD + tg * 4] = o;
        __syncthreads();
    }
}

// ---------------------------------------------------------------------------
__global__ __launch_bounds__(256) void ln_kernel(
    const float* __restrict__ x, const float* __restrict__ gamma,
    const float* __restrict__ beta, float* __restrict__ out)
{
    int row = blockIdx.x;
    int t = threadIdx.x;
    float4 a  = *(const float4*)&g_O[(size_t)row * CC + t * 4];
    float4 xv = *(const float4*)&x[(size_t)row * CC + t * 4];
    float4 r;
    r.x = a.x + xv.x; r.y = a.y + xv.y; r.z = a.z + xv.z; r.w = a.w + xv.w;
    float s  = r.x + r.y + r.z + r.w;
    float sq = r.x * r.x + r.y * r.y + r.z * r.z + r.w * r.w;
    #pragma unroll
    for (int off = 16; off; off >>= 1) {
        s  += __shfl_xor_sync(0xffffffffu, s, off);
        sq += __shfl_xor_sync(0xffffffffu, sq, off);
    }
    __shared__ float ss[8], ssq[8];
    __shared__ float mean_s, rstd_s;
    int w = t >> 5, lane = t & 31;
    if (lane == 0) { ss[w] = s; ssq[w] = sq; }
    __syncthreads();
    if (t == 0) {
        float S = 0.f, SQ = 0.f;
        #pragma unroll
        for (int i = 0; i < 8; i++) { S += ss[i]; SQ += ssq[i]; }
        float mean = S * (1.f / (float)CC);
        float var  = SQ * (1.f / (float)CC) - mean * mean;
        mean_s = mean;
        rstd_s = rsqrtf(var + 1e-12f);
    }
    __syncthreads();
    float mean = mean_s, rstd = rstd_s;
    float4 g  = *(const float4*)&gamma[t * 4];
    float4 be = *(const float4*)&beta[t * 4];
    float4 o;
    o.x = (r.x - mean) * rstd * g.x + be.x;
    o.y = (r.y - mean) * rstd * g.y + be.y;
    o.z = (r.z - mean) * rstd * g.z + be.z;
    o.w = (r.w - mean) * rstd * g.w + be.w;
    *(float4*)&out[(size_t)row * CC + t * 4] = o;
}

// ---------------------------------------------------------------------------
extern "C" void kernel_launch(void* const* d_in, const int* in_sizes, int n_in,
                              void* d_out, int out_size) {
    const float* x     = (const float*)d_in[0];
    const float* Wq    = (const float*)d_in[1];
    const float* bq    = (const float*)d_in[2];
    const float* Wk    = (const float*)d_in[3];
    const float* bk    = (const float*)d_in[4];
    const float* Wv    = (const float*)d_in[5];
    const float* bv    = (const float*)d_in[6];
    const float* gamma = (const float*)d_in[7];
    const float* beta  = (const float*)d_in[8];
    float* out = (float*)d_out;

    init_invfreq_kernel<<<1, 512>>>();

    split_x_kernel<<<MM * CC / 1024, 256>>>(x);
    split_w_kernel<<<dim3(CC * CC / 1024, 3), 256>>>(Wq, Wk, Wv);

    cudaFuncSetAttribute(gemm_mma_kernel,
                         cudaFuncAttributeMaxDynamicSharedMemorySize, GEMM_SMEM);
    dim3 ggrid(CC / 128, MM / 128, 3);               // (8, 128, 3)
    gemm_mma_kernel<<<ggrid, 256, GEMM_SMEM>>>(bq, bk, bv);

    kv_partial_kernel<<<dim3(BB * HH, NSPLIT), 256>>>();
    kv_reduce_kernel<<<BB * HH, 256>>>();
    out_kernel<<<dim3(BB * HH, NN / 32), 256>>>();
    ln_kernel<<<MM, 256>>>(x, gamma, beta, out);
}